// round 6
// baseline (speedup 1.0000x reference)
#include <cuda_runtime.h>

#define FULLMASK 0xffffffffu
#define NTAGS 32
#define BOS_IDX 30
#define EOS_IDX 31
#define L2E 1.4426950408889634f
#define LN2 0.6931471805599453f

typedef unsigned long long ull;

static __device__ __forceinline__ void ffma2(ull& d, ull a, ull b) {
    asm("fma.rn.f32x2 %0, %1, %2, %0;" : "+l"(d) : "l"(a), "l"(b));
}
static __device__ __forceinline__ ull add2(ull a, ull b) {
    ull r;
    asm("add.rn.f32x2 %0, %1, %2;" : "=l"(r) : "l"(a), "l"(b));
    return r;
}
static __device__ __forceinline__ float ex2_(float x) {
    float r; asm("ex2.approx.f32 %0, %1;" : "=f"(r) : "f"(x)); return r;
}
static __device__ __forceinline__ float lg2_(float x) {
    float r; asm("lg2.approx.f32 %0, %1;" : "=f"(r) : "f"(x)); return r;
}

// One warp per sequence, lane = tag. Multiplicative lag-1 recurrence:
//   s_j   = sum_i G[j,i] * beta_i          (G = exp(transitions), in regs)
//   beta' = s * K,  K = ex2(em*L2E - D),   D = lg2(s_EOS of previous step)
//   Csum += D; alpha materialized once at the end as lg2(beta)+Csum.
// No __syncwarp: lanes are convergent; lockstep issue orders LDS(t) before
// STS(t+1) and the per-warp in-order LSU orders STS(t) before LDS(t)
// (verified in R5: rel_err identical with/without the barrier).
__global__ __launch_bounds__(64, 1) void crf_forward_kernel(
    const float* __restrict__ emission,   // [B, T, 32]
    const float* __restrict__ trans,      // [32, 32]
    float* __restrict__ out,              // [B]
    int B, int T)
{
    const int lane = threadIdx.x & 31;
    const int w    = threadIdx.x >> 5;
    const int b    = blockIdx.x * 2 + w;

    __shared__ __align__(16) float sb[2][2][NTAGS];  // [warp][buf][tag]

    if (b >= B) return;  // warp-uniform

    // one-time: G row for this lane (exp of transitions), packed f32x2
    ull er[16];
    {
        const float* trow = trans + lane * NTAGS;
        #pragma unroll
        for (int q = 0; q < 16; q++) {
            float x = expf(trow[2 * q]);     // exp(-1000) -> 0 for BOS row
            float y = expf(trow[2 * q + 1]);
            asm("mov.b64 %0, {%1,%2};" : "=l"(er[q]) : "f"(x), "f"(y));
        }
    }

    const float* em = emission + (size_t)b * T * NTAGS + lane;

    // step 0 analytic (only BOS survives init alpha), log2 units, EOS-anchored
    float a2 = (em[0] + trans[lane * NTAGS + BOS_IDX]) * L2E;
    float Csum = __shfl_sync(FULLMASK, a2, EOS_IDX);
    float beta = ex2_(a2 - Csum);            // 0 on dead BOS lane
    float sEOSp = 1.0f;                      // => D = 0 on first iteration

    // emission prefetch ring, depth 4
    float ring[4];
    #pragma unroll
    for (int i = 0; i < 4; i++) {
        int tt = (i + 1 < T) ? (i + 1) : (T - 1);
        ring[i] = em[(size_t)tt * NTAGS];
    }

    const unsigned sa = (unsigned)__cvta_generic_to_shared(&sb[w][0][0]);

    #pragma unroll 4
    for (int t = 1; t < T; ++t) {
        float emv = ring[0];
        ring[0] = ring[1]; ring[1] = ring[2]; ring[2] = ring[3];
        int tp = (t + 4 < T) ? (t + 4) : (T - 1);
        ring[3] = em[(size_t)tp * NTAGS];

        // off-chain (lag-1): rescale constant from previous step's s_EOS
        float D = lg2_(sEOSp);
        Csum += D;
        float K = ex2_(fmaf(emv, L2E, -D));

        unsigned base = sa + (t & 1) * (NTAGS * 4);
        asm volatile("st.shared.f32 [%0], %1;"
                     :: "r"(base + lane * 4), "f"(beta) : "memory");
        // no __syncwarp: warp-convergent, in-order LSU (see header comment)

        // s_j = sum_i G[j,i]*beta_i : 8x LDS.128 -> 16x FFMA2, 8 accumulators
        ull A0 = 0ull, A1 = 0ull, A2 = 0ull, A3 = 0ull;
        ull A4 = 0ull, A5 = 0ull, A6 = 0ull, A7 = 0ull;
        #pragma unroll
        for (int q = 0; q < 4; q++) {
            ull p0, p1, p2, p3;
            asm volatile("ld.shared.v2.u64 {%0,%1}, [%2];"
                         : "=l"(p0), "=l"(p1) : "r"(base + q * 32));
            asm volatile("ld.shared.v2.u64 {%0,%1}, [%2];"
                         : "=l"(p2), "=l"(p3) : "r"(base + q * 32 + 16));
            if (q < 2) {
                ffma2(A0, er[4 * q + 0], p0);
                ffma2(A1, er[4 * q + 1], p1);
                ffma2(A2, er[4 * q + 2], p2);
                ffma2(A3, er[4 * q + 3], p3);
            } else {
                ffma2(A4, er[4 * q + 0], p0);
                ffma2(A5, er[4 * q + 1], p1);
                ffma2(A6, er[4 * q + 2], p2);
                ffma2(A7, er[4 * q + 3], p3);
            }
        }
        ull S = add2(add2(add2(A0, A1), add2(A2, A3)),
                     add2(add2(A4, A5), add2(A6, A7)));
        float sx, sy;
        asm("mov.b64 {%0,%1}, %2;" : "=f"(sx), "=f"(sy) : "l"(S));
        float s = sx + sy;

        sEOSp = __shfl_sync(FULLMASK, s, EOS_IDX);  // consumed next iter
        beta = s * K;                               // only on-chain math
    }

    // materialize alpha (log2 units) and terminal lse over the warp
    float ahat = lg2_(beta) + Csum;                 // -inf on BOS lane: ok
    float v = fmaf(trans[EOS_IDX * NTAGS + lane], L2E, ahat);
    float mm = v;
    #pragma unroll
    for (int o = 16; o; o >>= 1)
        mm = fmaxf(mm, __shfl_xor_sync(FULLMASK, mm, o));
    float ex = ex2_(v - mm);
    #pragma unroll
    for (int o = 16; o; o >>= 1)
        ex += __shfl_xor_sync(FULLMASK, ex, o);
    if (lane == 0)
        out[b] = (mm + lg2_(ex)) * LN2;
}

extern "C" void kernel_launch(void* const* d_in, const int* in_sizes, int n_in,
                              void* d_out, int out_size)
{
    const float* em = (const float*)d_in[0];
    const float* tr = (const float*)d_in[1];
    long long em_elems = in_sizes[0];
    if (n_in >= 2 && in_sizes[0] == NTAGS * NTAGS && in_sizes[1] > NTAGS * NTAGS) {
        em = (const float*)d_in[1];
        tr = (const float*)d_in[0];
        em_elems = in_sizes[1];
    }

    int B = out_size;
    int T = (int)(em_elems / ((long long)B * NTAGS));

    int blocks = (B + 1) / 2;  // 2 warps (2 sequences) per 64-thread CTA
    crf_forward_kernel<<<blocks, 64>>>(em, tr, (float*)d_out, B, T);
}

// round 7
// speedup vs baseline: 1.1490x; 1.1490x over previous
#include <cuda_runtime.h>

#define FULLMASK 0xffffffffu
#define NTAGS 32
#define BOS_IDX 30
#define EOS_IDX 31
#define L2E 1.4426950408889634f
#define LN2 0.6931471805599453f

typedef unsigned long long ull;

static __device__ __forceinline__ void ffma2(ull& d, ull a, ull b) {
    asm("fma.rn.f32x2 %0, %1, %2, %0;" : "+l"(d) : "l"(a), "l"(b));
}
static __device__ __forceinline__ ull add2(ull a, ull b) {
    ull r;
    asm("add.rn.f32x2 %0, %1, %2;" : "=l"(r) : "l"(a), "l"(b));
    return r;
}
static __device__ __forceinline__ float ex2_(float x) {
    float r; asm("ex2.approx.f32 %0, %1;" : "=f"(r) : "f"(x)); return r;
}
static __device__ __forceinline__ float lg2_(float x) {
    float r; asm("lg2.approx.f32 %0, %1;" : "=f"(r) : "f"(x)); return r;
}
static __device__ __forceinline__ float hsum2(ull a, ull b) {
    ull s = add2(a, b);
    float x, y;
    asm("mov.b64 {%0,%1}, %2;" : "=f"(x), "=f"(y) : "l"(s));
    return x + y;
}

// One warp per sequence, lane = tag. Multiplicative lag-1 recurrence:
//   s_j = sum_i G[j,i]*beta_i;  beta' = s*K;  K = ex2(em*L2E - D)
//   D = lg2(s_EOS prev step) off-chain; Csum += D; alpha = lg2(beta)+Csum at end.
// Split-dot exchange: lane l reads only its 16-beta half from smem (4 LDS.128),
// computes half-dots for rows l and l^16, then one shfl_xor(16) combines:
//   s_l = u_l + shfl_xor(w_l, 16).   Halves smem traffic vs full broadcast.
__global__ __launch_bounds__(64, 1) void crf_forward_kernel(
    const float* __restrict__ emission,   // [B, T, 32]
    const float* __restrict__ trans,      // [32, 32]
    float* __restrict__ out,              // [B]
    int B, int T)
{
    const int lane = threadIdx.x & 31;
    const int w    = threadIdx.x >> 5;
    const int b    = blockIdx.x * 2 + w;

    __shared__ __align__(16) float sb[2][2][NTAGS];  // [warp][buf][tag]

    if (b >= B) return;  // warp-uniform

    // G rows for this lane: row 'lane' and row 'lane^16', restricted to this
    // lane's beta-half (columns h..h+15), packed f32x2.
    const int h = lane & 16;              // 0 or 16: which beta-half we read
    const int pr = lane ^ 16;             // partner row
    ull eu[8], ew[8];
    {
        const float* r0 = trans + lane * NTAGS + h;
        const float* r1 = trans + pr   * NTAGS + h;
        #pragma unroll
        for (int q = 0; q < 8; q++) {
            float x = expf(r0[2 * q]);    // exp(-1000) -> 0 for BOS row
            float y = expf(r0[2 * q + 1]);
            asm("mov.b64 %0, {%1,%2};" : "=l"(eu[q]) : "f"(x), "f"(y));
            float z = expf(r1[2 * q]);
            float u = expf(r1[2 * q + 1]);
            asm("mov.b64 %0, {%1,%2};" : "=l"(ew[q]) : "f"(z), "f"(u));
        }
    }

    const float* em = emission + (size_t)b * T * NTAGS + lane;

    // step 0 analytic (only BOS survives init alpha), log2 units, EOS-anchored
    float a2 = (em[0] + trans[lane * NTAGS + BOS_IDX]) * L2E;
    float Csum = __shfl_sync(FULLMASK, a2, EOS_IDX);
    float beta = ex2_(a2 - Csum);            // 0 on dead BOS lane
    float sEOSp = 1.0f;                      // => D = 0 on first iteration

    // emission prefetch ring, depth 4
    float ring[4];
    #pragma unroll
    for (int i = 0; i < 4; i++) {
        int tt = (i + 1 < T) ? (i + 1) : (T - 1);
        ring[i] = em[(size_t)tt * NTAGS];
    }

    const unsigned sa = (unsigned)__cvta_generic_to_shared(&sb[w][0][0]);
    const unsigned hoff = (unsigned)h * 4;   // byte offset of this lane's half

    #pragma unroll 4
    for (int t = 1; t < T; ++t) {
        float emv = ring[0];
        ring[0] = ring[1]; ring[1] = ring[2]; ring[2] = ring[3];
        int tp = (t + 4 < T) ? (t + 4) : (T - 1);
        ring[3] = em[(size_t)tp * NTAGS];

        // off-chain (lag-1): rescale constant from previous step's s_EOS
        float D = lg2_(sEOSp);
        Csum += D;
        float K = ex2_(fmaf(emv, L2E, -D));

        unsigned base = sa + (t & 1) * (NTAGS * 4);
        asm volatile("st.shared.f32 [%0], %1;"
                     :: "r"(base + lane * 4), "f"(beta) : "memory");
        __syncwarp();

        // half-dots over this lane's beta-half: 4x LDS.128, 16x FFMA2
        unsigned hb = base + hoff;
        ull U0 = 0ull, U1 = 0ull, W0 = 0ull, W1 = 0ull;
        #pragma unroll
        for (int q = 0; q < 4; q++) {
            ull p0, p1;
            asm volatile("ld.shared.v2.u64 {%0,%1}, [%2];"
                         : "=l"(p0), "=l"(p1) : "r"(hb + q * 16));
            ffma2(U0, eu[2 * q],     p0);
            ffma2(U1, eu[2 * q + 1], p1);
            ffma2(W0, ew[2 * q],     p0);
            ffma2(W1, ew[2 * q + 1], p1);
        }
        float uu = hsum2(U0, U1);            // row 'lane', my half
        float ww = hsum2(W0, W1);            // row 'lane^16', my half
        float s = uu + __shfl_xor_sync(FULLMASK, ww, 16);

        sEOSp = __shfl_sync(FULLMASK, s, EOS_IDX);  // consumed next iter
        beta = s * K;                               // only on-chain math
    }

    // materialize alpha (log2 units) and terminal lse over the warp
    float ahat = lg2_(beta) + Csum;                 // -inf on BOS lane: ok
    float v = fmaf(trans[EOS_IDX * NTAGS + lane], L2E, ahat);
    float mm = v;
    #pragma unroll
    for (int o = 16; o; o >>= 1)
        mm = fmaxf(mm, __shfl_xor_sync(FULLMASK, mm, o));
    float ex = ex2_(v - mm);
    #pragma unroll
    for (int o = 16; o; o >>= 1)
        ex += __shfl_xor_sync(FULLMASK, ex, o);
    if (lane == 0)
        out[b] = (mm + lg2_(ex)) * LN2;
}

extern "C" void kernel_launch(void* const* d_in, const int* in_sizes, int n_in,
                              void* d_out, int out_size)
{
    const float* em = (const float*)d_in[0];
    const float* tr = (const float*)d_in[1];
    long long em_elems = in_sizes[0];
    if (n_in >= 2 && in_sizes[0] == NTAGS * NTAGS && in_sizes[1] > NTAGS * NTAGS) {
        em = (const float*)d_in[1];
        tr = (const float*)d_in[0];
        em_elems = in_sizes[1];
    }

    int B = out_size;
    int T = (int)(em_elems / ((long long)B * NTAGS));

    int blocks = (B + 1) / 2;  // 2 warps (2 sequences) per 64-thread CTA
    crf_forward_kernel<<<blocks, 64>>>(em, tr, (float*)d_out, B, T);
}